// round 15
// baseline (speedup 1.0000x reference)
#include <cuda_runtime.h>
#include <cstdint>

typedef unsigned long long ull;

#define D_DIM   128
#define K_DIM   32
#define N_PIX   4096
#define B_SZ    8
#define TILE_T  128
#define XSTRIDE 132   // x row stride: 16B-aligned rows; LDS.128 stage-A rows 2wf-optimal, stage-B cols conflict-free
#define CSTRIDE 132   // codeword row stride (16B aligned rows)
#define ASTRIDE 34    // A / Ered row stride in floats (17 ulls); 2*tb bank pattern keeps ull ops 1-wf

// shared-memory layout (float offsets)
#define X_OFF    0
#define C_OFF    (TILE_T * XSTRIDE)                  // 16896
#define A_OFF    (C_OFF + K_DIM * CSTRIDE)           // 21120 (ull aligned)
#define XSQ_OFF  (A_OFF + TILE_T * ASTRIDE)          // 25472
#define XSP_OFF  (XSQ_OFF + TILE_T)                  // 25600 (2 x 128 partials)
#define S_OFF    (XSP_OFF + 2 * TILE_T)              // 25856
#define BK_OFF   (S_OFF + K_DIM)                     // 25888
#define ASUM_OFF (BK_OFF + K_DIM)                    // 25920
#define SMEM_FLOATS (ASUM_OFF + K_DIM)               // 25952
#define SMEM_BYTES  (SMEM_FLOATS * 4)                // 103808 B -> 2 blocks/SM, single wave @ grid 256

// packed fp32x2 FMA (Blackwell): acc.lo += a.lo*b.lo ; acc.hi += a.hi*b.hi
__device__ __forceinline__ void ffma2(ull &acc, ull a, ull b) {
    asm("fma.rn.f32x2 %0, %1, %2, %0;" : "+l"(acc) : "l"(a), "l"(b));
}
__device__ __forceinline__ float2 u2f(ull v) {
    float2 r;
    asm("mov.b64 {%0, %1}, %2;" : "=f"(r.x), "=f"(r.y) : "l"(v));
    return r;
}
__device__ __forceinline__ ull f2u(float x, float y) {
    ull v;
    asm("mov.b64 %0, {%1, %2};" : "=l"(v) : "f"(x), "f"(y));
    return v;
}

__global__ void zero_kernel(float4* p, int n4) {
    int i = blockIdx.x * blockDim.x + threadIdx.x;
    if (i < n4) p[i] = make_float4(0.f, 0.f, 0.f, 0.f);
}

__global__ void __launch_bounds__(256, 2)
enc_kernel(const float* __restrict__ X,
           const float* __restrict__ CW,
           const float* __restrict__ SC,
           float* __restrict__ out)
{
    extern __shared__ float sm[];

    const int tid  = threadIdx.x;
    const int w    = tid >> 5;
    const int l    = tid & 31;
    const int b    = blockIdx.x >> 5;      // batch (32 tiles per batch)
    const int tile = blockIdx.x & 31;
    const int n0   = tile * TILE_T;

    // ---- load C (with fused csq warp-reduce), then X (with fused x^2 partials) ----
    {
        // zero asum accumulators (used by softmax smem atomics later)
        if (tid < K_DIM) sm[ASUM_OFF + tid] = 0.0f;

        // codewords: quad c = tid + 256*s belongs to row k = w + 8*s, quad index l.
        // So per s, a warp-reduce of the lane quad-sums gives csq[w + 8*s] directly.
        float qss[4];
        #pragma unroll
        for (int s = 0; s < 4; s++) {
            int c = tid + 256 * s;             // 0..1023 quads
            int k = c >> 5;                    // = w + 8*s (uniform per warp)
            int dc = (c & 31) * 4;             // = 4*l
            float4 v = *(const float4*)(CW + 4 * c);
            *(float4*)(sm + C_OFF + k * CSTRIDE + dc) = v;
            qss[s] = v.x * v.x + v.y * v.y + v.z * v.z + v.w * v.w;
        }
        float sc_l = (l < 4) ? SC[w + 8 * l] : 0.0f;   // lane j holds SC[w+8j]
        #pragma unroll
        for (int o = 16; o > 0; o >>= 1) {
            qss[0] += __shfl_xor_sync(0xffffffffu, qss[0], o);
            qss[1] += __shfl_xor_sync(0xffffffffu, qss[1], o);
            qss[2] += __shfl_xor_sync(0xffffffffu, qss[2], o);
            qss[3] += __shfl_xor_sync(0xffffffffu, qss[3], o);
        }
        if (l < 4) {
            int k = w + 8 * l;
            float ss = (l == 0) ? qss[0] : (l == 1) ? qss[1] : (l == 2) ? qss[2] : qss[3];
            sm[S_OFF + k]  = sc_l;
            sm[BK_OFF + k] = ss * sc_l;
        }

        // X tile [128 d][128 t] -> x_sh[t][132] via d-quads: 4 LDG.32 + 1 STS.128,
        // folding per-pixel x^2 partials. thread: t = tid&127, quads q = dh + 2*s.
        const float* Xb = X + (size_t)b * D_DIM * N_PIX + n0;
        const int tl = tid & 127;
        const int dh = tid >> 7;
        float ssq = 0.0f;
        #pragma unroll 4
        for (int s = 0; s < 16; s++) {
            int q = dh + 2 * s;                // quad 0..31, d = 4q..4q+3
            int d0 = 4 * q;
            float v0 = Xb[(size_t)(d0 + 0) * N_PIX + tl];
            float v1 = Xb[(size_t)(d0 + 1) * N_PIX + tl];
            float v2 = Xb[(size_t)(d0 + 2) * N_PIX + tl];
            float v3 = Xb[(size_t)(d0 + 3) * N_PIX + tl];
            ssq = fmaf(v0, v0, ssq); ssq = fmaf(v1, v1, ssq);
            ssq = fmaf(v2, v2, ssq); ssq = fmaf(v3, v3, ssq);
            *(float4*)(sm + X_OFF + tl * XSTRIDE + d0) = make_float4(v0, v1, v2, v3);
        }
        sm[XSP_OFF + dh * TILE_T + tl] = ssq;
    }
    __syncthreads();

    // ---- finalize xsq ----
    if (tid < TILE_T)
        sm[XSQ_OFF + tid] = sm[XSP_OFF + tid] + sm[XSP_OFF + TILE_T + tid];
    __syncthreads();

    // ---- Stage A: cross[t][k] = sum_d x[t][d]*c[k][d]; 8t x 4k tile, d-pair acc, 2-way d split ----
    // g = w>>2 (d-half 64), lanes: tb = l&15, lh = l>>4; kb = 2*(w&3)+lh in [0,8); k = 4kb+jj.
    // d-quad macro step: xv/cv as ulonglong2 (2 d-pairs). xv: 16 lanes x 16B = 2 wf (optimal);
    // cv: 2 addrs x 16B (rows 4 apart -> bank offset 16) = 1 wf.
    const int g  = w >> 2;
    const int tb = l & 15;
    const int lh = l >> 4;
    {
        const int kb = 2 * (w & 3) + lh;

        ull acc[8][4];
        #pragma unroll
        for (int i = 0; i < 8; i++)
            #pragma unroll
            for (int jj = 0; jj < 4; jj++) acc[i][jj] = 0ULL;

        const float* xr = sm + X_OFF + tb * XSTRIDE + 64 * g;
        const float* cr = sm + C_OFF + (4 * kb) * CSTRIDE + 64 * g;

        #pragma unroll 1
        for (int dq = 0; dq < 16; dq++) {
            int d4 = 4 * dq;
            ulonglong2 cv[4];
            #pragma unroll
            for (int jj = 0; jj < 4; jj++)
                cv[jj] = *(const ulonglong2*)(cr + jj * CSTRIDE + d4);
            #pragma unroll
            for (int i = 0; i < 8; i++) {
                ulonglong2 xv = *(const ulonglong2*)(xr + (16 * i) * XSTRIDE + d4);
                ffma2(acc[i][0], xv.x, cv[0].x); ffma2(acc[i][0], xv.y, cv[0].y);
                ffma2(acc[i][1], xv.x, cv[1].x); ffma2(acc[i][1], xv.y, cv[1].y);
                ffma2(acc[i][2], xv.x, cv[2].x); ffma2(acc[i][2], xv.y, cv[2].y);
                ffma2(acc[i][3], xv.x, cv[3].x); ffma2(acc[i][3], xv.y, cv[3].y);
            }
        }

        // g==1 writes partial cross pairs (k,k+1) into A[t][k] (float offset = k)
        if (g == 1) {
            #pragma unroll
            for (int i = 0; i < 8; i++) {
                int t = tb + 16 * i;
                #pragma unroll
                for (int jp = 0; jp < 2; jp++) {
                    float2 p0 = u2f(acc[i][2 * jp]);
                    float2 p1 = u2f(acc[i][2 * jp + 1]);
                    *(ull*)(sm + A_OFF + t * ASTRIDE + 4 * kb + 2 * jp) =
                        f2u(p0.x + p0.y, p1.x + p1.y);
                }
            }
        }
        __syncthreads();
        // g==0 adds its partial, computes logits, writes back in place
        if (g == 0) {
            float sv[4], bv[4];
            #pragma unroll
            for (int jj = 0; jj < 4; jj++) {
                sv[jj] = sm[S_OFF + 4 * kb + jj];
                bv[jj] = sm[BK_OFF + 4 * kb + jj];
            }
            #pragma unroll
            for (int i = 0; i < 8; i++) {
                int t = tb + 16 * i;
                float xsq = sm[XSQ_OFF + t];
                #pragma unroll
                for (int jp = 0; jp < 2; jp++) {
                    ull* addr = (ull*)(sm + A_OFF + t * ASTRIDE + 4 * kb + 2 * jp);
                    float2 oth = u2f(*addr);
                    float2 p0 = u2f(acc[i][2 * jp]);
                    float2 p1 = u2f(acc[i][2 * jp + 1]);
                    float cr0 = oth.x + p0.x + p0.y;
                    float cr1 = oth.y + p1.x + p1.y;
                    float lg0 = fmaf(sv[2 * jp],     fmaf(-2.0f, cr0, xsq), bv[2 * jp]);
                    float lg1 = fmaf(sv[2 * jp + 1], fmaf(-2.0f, cr1, xsq), bv[2 * jp + 1]);
                    *addr = f2u(lg0, lg1);
                }
            }
        }
    }
    __syncthreads();

    // ---- Softmax over k (lane = k): warp w handles px [16w, 16w+16); no max pass ----
    // per-warp asum partial merged via smem float atomics (spread addresses, 1 per lane).
    {
        float asum_l = 0.0f;
        #pragma unroll
        for (int q = 0; q < 4; q++) {
            int t0 = w * 16 + 4 * q;
            float v0 = sm[A_OFF + (t0 + 0) * ASTRIDE + l];
            float v1 = sm[A_OFF + (t0 + 1) * ASTRIDE + l];
            float v2 = sm[A_OFF + (t0 + 2) * ASTRIDE + l];
            float v3 = sm[A_OFF + (t0 + 3) * ASTRIDE + l];
            float e0 = __expf(v0), e1 = __expf(v1);
            float e2 = __expf(v2), e3 = __expf(v3);
            float s0 = e0, s1 = e1, s2 = e2, s3 = e3;
            #pragma unroll
            for (int o = 16; o > 0; o >>= 1) {
                s0 += __shfl_xor_sync(0xffffffffu, s0, o);
                s1 += __shfl_xor_sync(0xffffffffu, s1, o);
                s2 += __shfl_xor_sync(0xffffffffu, s2, o);
                s3 += __shfl_xor_sync(0xffffffffu, s3, o);
            }
            float a0 = e0 * __fdividef(1.0f, s0);
            float a1 = e1 * __fdividef(1.0f, s1);
            float a2 = e2 * __fdividef(1.0f, s2);
            float a3 = e3 * __fdividef(1.0f, s3);
            sm[A_OFF + (t0 + 0) * ASTRIDE + l] = a0;
            sm[A_OFF + (t0 + 1) * ASTRIDE + l] = a1;
            sm[A_OFF + (t0 + 2) * ASTRIDE + l] = a2;
            sm[A_OFF + (t0 + 3) * ASTRIDE + l] = a3;
            asum_l += a0 + a1 + a2 + a3;
        }
        atomicAdd(sm + ASUM_OFF + l, asum_l);      // lane l = codeword l
    }
    __syncthreads();

    // ---- Stage B: E[k][d] = sum_t A[k][t]*x[t][d]; 8k x 4d tile, k-pair acc, 2-way t split ----
    // gB = w>>2 (t-half), kbB = w&3 (k-octet, uniform per warp), db = l; d = db + 32*j.
    {
        const int gB  = w >> 2;
        const int kbB = w & 3;
        const int db  = l;

        ull acc2[4][4];
        #pragma unroll
        for (int jj = 0; jj < 4; jj++)
            #pragma unroll
            for (int j = 0; j < 4; j++) acc2[jj][j] = 0ULL;

        const int t0 = 64 * gB;
        #pragma unroll 2
        for (int tt = 0; tt < 64; tt++) {
            int t = t0 + tt;
            const float* xrow = sm + X_OFF + t * XSTRIDE + db;
            ull xx[4];
            #pragma unroll
            for (int j = 0; j < 4; j++) {
                float xv = xrow[32 * j];
                xx[j] = f2u(xv, xv);
            }
            const float* Ar = sm + A_OFF + t * ASTRIDE + 8 * kbB;
            ull av0 = *(const ull*)(Ar + 0);
            ull av1 = *(const ull*)(Ar + 2);
            ull av2 = *(const ull*)(Ar + 4);
            ull av3 = *(const ull*)(Ar + 6);
            #pragma unroll
            for (int j = 0; j < 4; j++) {
                ffma2(acc2[0][j], av0, xx[j]);
                ffma2(acc2[1][j], av1, xx[j]);
                ffma2(acc2[2][j], av2, xx[j]);
                ffma2(acc2[3][j], av3, xx[j]);
            }
        }
        __syncthreads();           // all A reads done; A region becomes Ered[d][k]

        if (gB == 0) {             // write partials: Ered row d, float offset = k
            #pragma unroll
            for (int jj = 0; jj < 4; jj++)
                #pragma unroll
                for (int j = 0; j < 4; j++) {
                    int d = db + 32 * j;
                    *(ull*)(sm + A_OFF + d * ASTRIDE + 8 * kbB + 2 * jj) = acc2[jj][j];
                }
        }
        __syncthreads();
        if (gB == 1) {             // add own partial, fold -asum*c, atomic merge
            float* Eb = out + (size_t)b * K_DIM * D_DIM;
            #pragma unroll
            for (int jj = 0; jj < 4; jj++) {
                int k0 = 8 * kbB + 2 * jj;
                float as0 = sm[ASUM_OFF + k0];
                float as1 = sm[ASUM_OFF + k0 + 1];
                #pragma unroll
                for (int j = 0; j < 4; j++) {
                    int d = db + 32 * j;
                    float2 mine = u2f(acc2[jj][j]);
                    float2 oth  = u2f(*(const ull*)(sm + A_OFF + d * ASTRIDE + k0));
                    float v0 = fmaf(-as0, sm[C_OFF + k0 * CSTRIDE + d],       mine.x + oth.x);
                    float v1 = fmaf(-as1, sm[C_OFF + (k0 + 1) * CSTRIDE + d], mine.y + oth.y);
                    atomicAdd(Eb + k0 * D_DIM + d,           v0);
                    atomicAdd(Eb + (k0 + 1) * D_DIM + d,     v1);
                }
            }
        }
    }
}

extern "C" void kernel_launch(void* const* d_in, const int* in_sizes, int n_in,
                              void* d_out, int out_size)
{
    const float* X  = (const float*)d_in[0];
    const float* CW = (const float*)d_in[1];
    const float* SC = (const float*)d_in[2];
    float* out = (float*)d_out;

    cudaFuncSetAttribute(enc_kernel, cudaFuncAttributeMaxDynamicSharedMemorySize, SMEM_BYTES);

    const int OUT_N4 = (B_SZ * K_DIM * D_DIM) / 4;      // 8192 float4
    zero_kernel<<<OUT_N4 / 256, 256>>>((float4*)out, OUT_N4);
    enc_kernel<<<B_SZ * (N_PIX / TILE_T), 256, SMEM_BYTES>>>(X, CW, SC, out);
}

// round 16
// speedup vs baseline: 1.0125x; 1.0125x over previous
#include <cuda_runtime.h>
#include <cstdint>

typedef unsigned long long ull;

#define D_DIM   128
#define K_DIM   32
#define N_PIX   4096
#define B_SZ    8
#define TILE_T  128
#define XSTRIDE 132   // x row stride: 16B-aligned rows; LDS.128 stage-A rows 2wf-optimal, stage-B cols conflict-free
#define CSTRIDE 132   // codeword row stride (16B aligned rows)
#define ASTRIDE 34    // A row stride in floats (17 ulls); 2*tb bank pattern keeps ull ops 1-wf

// shared-memory layout (float offsets)
#define X_OFF    0
#define C_OFF    (TILE_T * XSTRIDE)                  // 16896
#define A_OFF    (C_OFF + K_DIM * CSTRIDE)           // 21120 (ull aligned)
#define XSQ_OFF  (A_OFF + TILE_T * ASTRIDE)          // 25472
#define XSP_OFF  (XSQ_OFF + TILE_T)                  // 25600 (2 x 128 partials)
#define S_OFF    (XSP_OFF + 2 * TILE_T)              // 25856
#define BK_OFF   (S_OFF + K_DIM)                     // 25888
#define ASUM_OFF (BK_OFF + K_DIM)                    // 25920
#define SMEM_FLOATS (ASUM_OFF + K_DIM)               // 25952
#define SMEM_BYTES  (SMEM_FLOATS * 4)                // 103808 B -> 2 blocks/SM, single wave @ grid 256

// packed fp32x2 FMA (Blackwell): acc.lo += a.lo*b.lo ; acc.hi += a.hi*b.hi
__device__ __forceinline__ void ffma2(ull &acc, ull a, ull b) {
    asm("fma.rn.f32x2 %0, %1, %2, %0;" : "+l"(acc) : "l"(a), "l"(b));
}
__device__ __forceinline__ float2 u2f(ull v) {
    float2 r;
    asm("mov.b64 {%0, %1}, %2;" : "=f"(r.x), "=f"(r.y) : "l"(v));
    return r;
}
__device__ __forceinline__ ull f2u(float x, float y) {
    ull v;
    asm("mov.b64 %0, {%1, %2};" : "=l"(v) : "f"(x), "f"(y));
    return v;
}

__global__ void zero_kernel(float4* p, int n4) {
    int i = blockIdx.x * blockDim.x + threadIdx.x;
    if (i < n4) p[i] = make_float4(0.f, 0.f, 0.f, 0.f);
}

__global__ void __launch_bounds__(256, 2)
enc_kernel(const float* __restrict__ X,
           const float* __restrict__ CW,
           const float* __restrict__ SC,
           float* __restrict__ out)
{
    extern __shared__ float sm[];

    const int tid  = threadIdx.x;
    const int w    = tid >> 5;
    const int l    = tid & 31;
    const int b    = blockIdx.x >> 5;      // batch (32 tiles per batch)
    const int tile = blockIdx.x & 31;
    const int n0   = tile * TILE_T;

    // ---- load C (with fused csq warp-reduce), then X (with fused x^2 partials) ----
    {
        // zero asum accumulators (used by softmax smem atomics later)
        if (tid < K_DIM) sm[ASUM_OFF + tid] = 0.0f;

        // codewords: quad c = tid + 256*s belongs to row k = w + 8*s, quad index l.
        // So per s, a warp-reduce of the lane quad-sums gives csq[w + 8*s] directly.
        float qss[4];
        #pragma unroll
        for (int s = 0; s < 4; s++) {
            int c = tid + 256 * s;             // 0..1023 quads
            int k = c >> 5;                    // = w + 8*s (uniform per warp)
            int dc = (c & 31) * 4;             // = 4*l
            float4 v = *(const float4*)(CW + 4 * c);
            *(float4*)(sm + C_OFF + k * CSTRIDE + dc) = v;
            qss[s] = v.x * v.x + v.y * v.y + v.z * v.z + v.w * v.w;
        }
        float sc_l = (l < 4) ? SC[w + 8 * l] : 0.0f;   // lane j holds SC[w+8j]
        #pragma unroll
        for (int o = 16; o > 0; o >>= 1) {
            qss[0] += __shfl_xor_sync(0xffffffffu, qss[0], o);
            qss[1] += __shfl_xor_sync(0xffffffffu, qss[1], o);
            qss[2] += __shfl_xor_sync(0xffffffffu, qss[2], o);
            qss[3] += __shfl_xor_sync(0xffffffffu, qss[3], o);
        }
        if (l < 4) {
            int k = w + 8 * l;
            float ss = (l == 0) ? qss[0] : (l == 1) ? qss[1] : (l == 2) ? qss[2] : qss[3];
            sm[S_OFF + k]  = sc_l;
            sm[BK_OFF + k] = ss * sc_l;
        }

        // X tile [128 d][128 t] -> x_sh[t][132] via d-quads: 4 LDG.32 + 1 STS.128,
        // folding per-pixel x^2 partials. thread: t = tid&127, quads q = dh + 2*s.
        const float* Xb = X + (size_t)b * D_DIM * N_PIX + n0;
        const int tl = tid & 127;
        const int dh = tid >> 7;
        float ssq = 0.0f;
        #pragma unroll 4
        for (int s = 0; s < 16; s++) {
            int q = dh + 2 * s;                // quad 0..31, d = 4q..4q+3
            int d0 = 4 * q;
            float v0 = Xb[(size_t)(d0 + 0) * N_PIX + tl];
            float v1 = Xb[(size_t)(d0 + 1) * N_PIX + tl];
            float v2 = Xb[(size_t)(d0 + 2) * N_PIX + tl];
            float v3 = Xb[(size_t)(d0 + 3) * N_PIX + tl];
            ssq = fmaf(v0, v0, ssq); ssq = fmaf(v1, v1, ssq);
            ssq = fmaf(v2, v2, ssq); ssq = fmaf(v3, v3, ssq);
            *(float4*)(sm + X_OFF + tl * XSTRIDE + d0) = make_float4(v0, v1, v2, v3);
        }
        sm[XSP_OFF + dh * TILE_T + tl] = ssq;
    }
    __syncthreads();

    // ---- Stage A: cross[t][k] = sum_d x[t][d]*c[k][d]; 8t x 4k tile, d-pair acc, 2-way d split ----
    // g = w>>2 (d-half 64), lanes: tb = l&15, lh = l>>4; kb = 2*(w&3)+lh in [0,8); k = 4kb+jj.
    // d-quad macro step: xv/cv as ulonglong2 (2 d-pairs). xv: 16 lanes x 16B = 2 wf (optimal);
    // cv: 2 addrs x 16B (rows 4 apart -> bank offset 16) = 1 wf.
    const int g  = w >> 2;
    const int tb = l & 15;
    const int lh = l >> 4;
    {
        const int kb = 2 * (w & 3) + lh;

        ull acc[8][4];
        #pragma unroll
        for (int i = 0; i < 8; i++)
            #pragma unroll
            for (int jj = 0; jj < 4; jj++) acc[i][jj] = 0ULL;

        const float* xr = sm + X_OFF + tb * XSTRIDE + 64 * g;
        const float* cr = sm + C_OFF + (4 * kb) * CSTRIDE + 64 * g;

        #pragma unroll 1
        for (int dq = 0; dq < 16; dq++) {
            int d4 = 4 * dq;
            ulonglong2 cv[4];
            #pragma unroll
            for (int jj = 0; jj < 4; jj++)
                cv[jj] = *(const ulonglong2*)(cr + jj * CSTRIDE + d4);
            #pragma unroll
            for (int i = 0; i < 8; i++) {
                ulonglong2 xv = *(const ulonglong2*)(xr + (16 * i) * XSTRIDE + d4);
                ffma2(acc[i][0], xv.x, cv[0].x); ffma2(acc[i][0], xv.y, cv[0].y);
                ffma2(acc[i][1], xv.x, cv[1].x); ffma2(acc[i][1], xv.y, cv[1].y);
                ffma2(acc[i][2], xv.x, cv[2].x); ffma2(acc[i][2], xv.y, cv[2].y);
                ffma2(acc[i][3], xv.x, cv[3].x); ffma2(acc[i][3], xv.y, cv[3].y);
            }
        }

        // xsq finalize rides here (pre-mid-sync); consumer (g==0 epilogue) is post-mid-sync.
        if (tid < TILE_T)
            sm[XSQ_OFF + tid] = sm[XSP_OFF + tid] + sm[XSP_OFF + TILE_T + tid];

        // g==1 writes partial cross pairs (k,k+1) into A[t][k] (float offset = k)
        if (g == 1) {
            #pragma unroll
            for (int i = 0; i < 8; i++) {
                int t = tb + 16 * i;
                #pragma unroll
                for (int jp = 0; jp < 2; jp++) {
                    float2 p0 = u2f(acc[i][2 * jp]);
                    float2 p1 = u2f(acc[i][2 * jp + 1]);
                    *(ull*)(sm + A_OFF + t * ASTRIDE + 4 * kb + 2 * jp) =
                        f2u(p0.x + p0.y, p1.x + p1.y);
                }
            }
        }
        __syncthreads();
        // g==0 adds its partial, computes logits, writes back in place
        if (g == 0) {
            float sv[4], bv[4];
            #pragma unroll
            for (int jj = 0; jj < 4; jj++) {
                sv[jj] = sm[S_OFF + 4 * kb + jj];
                bv[jj] = sm[BK_OFF + 4 * kb + jj];
            }
            #pragma unroll
            for (int i = 0; i < 8; i++) {
                int t = tb + 16 * i;
                float xsq = sm[XSQ_OFF + t];
                #pragma unroll
                for (int jp = 0; jp < 2; jp++) {
                    ull* addr = (ull*)(sm + A_OFF + t * ASTRIDE + 4 * kb + 2 * jp);
                    float2 oth = u2f(*addr);
                    float2 p0 = u2f(acc[i][2 * jp]);
                    float2 p1 = u2f(acc[i][2 * jp + 1]);
                    float cr0 = oth.x + p0.x + p0.y;
                    float cr1 = oth.y + p1.x + p1.y;
                    float lg0 = fmaf(sv[2 * jp],     fmaf(-2.0f, cr0, xsq), bv[2 * jp]);
                    float lg1 = fmaf(sv[2 * jp + 1], fmaf(-2.0f, cr1, xsq), bv[2 * jp + 1]);
                    *addr = f2u(lg0, lg1);
                }
            }
        }
    }
    __syncthreads();

    // ---- Softmax over k (lane = k): warp w handles px [16w, 16w+16); no max pass ----
    // per-warp asum partial merged via smem float atomics (spread addresses, 1 per lane).
    {
        float asum_l = 0.0f;
        #pragma unroll
        for (int q = 0; q < 4; q++) {
            int t0 = w * 16 + 4 * q;
            float v0 = sm[A_OFF + (t0 + 0) * ASTRIDE + l];
            float v1 = sm[A_OFF + (t0 + 1) * ASTRIDE + l];
            float v2 = sm[A_OFF + (t0 + 2) * ASTRIDE + l];
            float v3 = sm[A_OFF + (t0 + 3) * ASTRIDE + l];
            float e0 = __expf(v0), e1 = __expf(v1);
            float e2 = __expf(v2), e3 = __expf(v3);
            float s0 = e0, s1 = e1, s2 = e2, s3 = e3;
            #pragma unroll
            for (int o = 16; o > 0; o >>= 1) {
                s0 += __shfl_xor_sync(0xffffffffu, s0, o);
                s1 += __shfl_xor_sync(0xffffffffu, s1, o);
                s2 += __shfl_xor_sync(0xffffffffu, s2, o);
                s3 += __shfl_xor_sync(0xffffffffu, s3, o);
            }
            float a0 = e0 * __fdividef(1.0f, s0);
            float a1 = e1 * __fdividef(1.0f, s1);
            float a2 = e2 * __fdividef(1.0f, s2);
            float a3 = e3 * __fdividef(1.0f, s3);
            sm[A_OFF + (t0 + 0) * ASTRIDE + l] = a0;
            sm[A_OFF + (t0 + 1) * ASTRIDE + l] = a1;
            sm[A_OFF + (t0 + 2) * ASTRIDE + l] = a2;
            sm[A_OFF + (t0 + 3) * ASTRIDE + l] = a3;
            asum_l += a0 + a1 + a2 + a3;
        }
        atomicAdd(sm + ASUM_OFF + l, asum_l);      // lane l = codeword l
    }
    __syncthreads();

    // ---- Stage B: E[k][d] = sum_t A[k][t]*x[t][d]; 8k x 4d tile, k-pair acc, 2-way t split ----
    // gB = w>>2 (t-half), kbB = w&3 (k-octet, uniform per warp), db = l; d = db + 32*j.
    // Both halves atomic their partials directly (no smem exchange, no trailing barriers);
    // gB==1 folds -asum*c exactly once.
    {
        const int gB  = w >> 2;
        const int kbB = w & 3;
        const int db  = l;

        ull acc2[4][4];
        #pragma unroll
        for (int jj = 0; jj < 4; jj++)
            #pragma unroll
            for (int j = 0; j < 4; j++) acc2[jj][j] = 0ULL;

        const int t0 = 64 * gB;
        #pragma unroll 2
        for (int tt = 0; tt < 64; tt++) {
            int t = t0 + tt;
            const float* xrow = sm + X_OFF + t * XSTRIDE + db;
            ull xx[4];
            #pragma unroll
            for (int j = 0; j < 4; j++) {
                float xv = xrow[32 * j];
                xx[j] = f2u(xv, xv);
            }
            const float* Ar = sm + A_OFF + t * ASTRIDE + 8 * kbB;
            ull av0 = *(const ull*)(Ar + 0);
            ull av1 = *(const ull*)(Ar + 2);
            ull av2 = *(const ull*)(Ar + 4);
            ull av3 = *(const ull*)(Ar + 6);
            #pragma unroll
            for (int j = 0; j < 4; j++) {
                ffma2(acc2[0][j], av0, xx[j]);
                ffma2(acc2[1][j], av1, xx[j]);
                ffma2(acc2[2][j], av2, xx[j]);
                ffma2(acc2[3][j], av3, xx[j]);
            }
        }

        float* Eb = out + (size_t)b * K_DIM * D_DIM;
        #pragma unroll
        for (int jj = 0; jj < 4; jj++) {
            int k0 = 8 * kbB + 2 * jj;
            float2 v01 = u2f(acc2[jj][0]);
            float2 v23_0 = u2f(acc2[jj][1]);
            float2 v23_1 = u2f(acc2[jj][2]);
            float2 v23_2 = u2f(acc2[jj][3]);
            float vk0[4] = {v01.x, v23_0.x, v23_1.x, v23_2.x};
            float vk1[4] = {v01.y, v23_0.y, v23_1.y, v23_2.y};
            if (gB == 1) {
                float as0 = sm[ASUM_OFF + k0];
                float as1 = sm[ASUM_OFF + k0 + 1];
                #pragma unroll
                for (int j = 0; j < 4; j++) {
                    int d = db + 32 * j;
                    vk0[j] = fmaf(-as0, sm[C_OFF + k0 * CSTRIDE + d],       vk0[j]);
                    vk1[j] = fmaf(-as1, sm[C_OFF + (k0 + 1) * CSTRIDE + d], vk1[j]);
                }
            }
            #pragma unroll
            for (int j = 0; j < 4; j++) {
                int d = db + 32 * j;
                atomicAdd(Eb + k0 * D_DIM + d,       vk0[j]);
                atomicAdd(Eb + (k0 + 1) * D_DIM + d, vk1[j]);
            }
        }
    }
}

extern "C" void kernel_launch(void* const* d_in, const int* in_sizes, int n_in,
                              void* d_out, int out_size)
{
    const float* X  = (const float*)d_in[0];
    const float* CW = (const float*)d_in[1];
    const float* SC = (const float*)d_in[2];
    float* out = (float*)d_out;

    cudaFuncSetAttribute(enc_kernel, cudaFuncAttributeMaxDynamicSharedMemorySize, SMEM_BYTES);

    const int OUT_N4 = (B_SZ * K_DIM * D_DIM) / 4;      // 8192 float4
    zero_kernel<<<OUT_N4 / 256, 256>>>((float4*)out, OUT_N4);
    enc_kernel<<<B_SZ * (N_PIX / TILE_T), 256, SMEM_BYTES>>>(X, CW, SC, out);
}